// round 14
// baseline (speedup 1.0000x reference)
#include <cuda_runtime.h>
#include <cuda_bf16.h>
#include <cstdint>

#define Bsz 128
#define Tsz 1024
#define Dsz 256
#define Hsz 256

typedef unsigned long long u64;

// ---------------- scratch ----------
__device__ float g_xproj[(size_t)Bsz * Tsz * 3 * Hsz];
__device__ __nv_bfloat16 g_a_hi[(size_t)Bsz * Tsz * Dsz];
__device__ __nv_bfloat16 g_a_lo[(size_t)Bsz * Tsz * Dsz];
__device__ __nv_bfloat16 g_wt_hi[768 * 256];
__device__ __nv_bfloat16 g_wt_lo[768 * 256];
__device__ int g_done_mode;

__device__ __forceinline__ uint32_t smem_u32(const void* p) {
    uint32_t a;
    asm("{ .reg .u64 t; cvta.to.shared.u64 t, %1; cvt.u32.u64 %0, t; }"
        : "=r"(a) : "l"(p));
    return a;
}
__device__ __forceinline__ void cp16(uint32_t s, const void* g) {
    asm volatile("cp.async.cg.shared.global [%0], [%1], 16;"
                 :: "r"(s), "l"(__cvta_generic_to_global(g)) : "memory");
}
#define LDSM4(r, addr) \
    asm volatile("ldmatrix.sync.aligned.m8n8.x4.shared.b16 {%0,%1,%2,%3}, [%4];" \
                 : "=r"((r)[0]), "=r"((r)[1]), "=r"((r)[2]), "=r"((r)[3]) : "r"(addr))
#define LDSM2(r0, r1, addr) \
    asm volatile("ldmatrix.sync.aligned.m8n8.x2.shared.b16 {%0,%1}, [%2];" \
                 : "=r"(r0), "=r"(r1) : "r"(addr))
#define MMA(c, A, b0, b1) \
    asm volatile("mma.sync.aligned.m16n8k16.row.col.f32.bf16.bf16.f32 " \
                 "{%0,%1,%2,%3},{%4,%5,%6,%7},{%8,%9},{%0,%1,%2,%3};" \
                 : "+f"((c)[0]), "+f"((c)[1]), "+f"((c)[2]), "+f"((c)[3]) \
                 : "r"((A)[0]), "r"((A)[1]), "r"((A)[2]), "r"((A)[3]), \
                   "r"(b0), "r"(b1))
// A rows 8-15 duplicate rows 0-7 (D rows 8-15 = dup, ignored); a0=k0-7, a1=k8-15
#define MMA_DUP(c, a0, a1, b0, b1) \
    asm volatile("mma.sync.aligned.m16n8k16.row.col.f32.bf16.bf16.f32 " \
                 "{%0,%1,%2,%3},{%4,%5,%6,%7},{%8,%9},{%0,%1,%2,%3};" \
                 : "+f"((c)[0]), "+f"((c)[1]), "+f"((c)[2]), "+f"((c)[3]) \
                 : "r"(a0), "r"(a0), "r"(a1), "r"(a1), "r"(b0), "r"(b1))

// ---------------------------------------------------------------------------
__global__ void detect_done_kernel(const unsigned int* __restrict__ done_words)
{
    int i = blockIdx.x * blockDim.x + threadIdx.x;
    if (done_words[i] > 1u) atomicOr(&g_done_mode, 1);
}

__global__ void decompose_obs(const float* __restrict__ src)
{
    size_t i = (size_t)blockIdx.x * blockDim.x + threadIdx.x;
    float4 v = ((const float4*)src)[i];
    __nv_bfloat16 h0 = __float2bfloat16(v.x);
    __nv_bfloat16 h1 = __float2bfloat16(v.y);
    __nv_bfloat16 h2 = __float2bfloat16(v.z);
    __nv_bfloat16 h3 = __float2bfloat16(v.w);
    __nv_bfloat16 l0 = __float2bfloat16(v.x - __bfloat162float(h0));
    __nv_bfloat16 l1 = __float2bfloat16(v.y - __bfloat162float(h1));
    __nv_bfloat16 l2 = __float2bfloat16(v.z - __bfloat162float(h2));
    __nv_bfloat16 l3 = __float2bfloat16(v.w - __bfloat162float(h3));
    __nv_bfloat162* hp = (__nv_bfloat162*)g_a_hi;
    __nv_bfloat162* lp = (__nv_bfloat162*)g_a_lo;
    hp[2 * i]     = __nv_bfloat162(h0, h1);
    hp[2 * i + 1] = __nv_bfloat162(h2, h3);
    lp[2 * i]     = __nv_bfloat162(l0, l1);
    lp[2 * i + 1] = __nv_bfloat162(l2, l3);
}

__global__ void decompose_wi(const float* __restrict__ Wi)
{
    int idx = blockIdx.x * blockDim.x + threadIdx.x;
    int k = idx / 768, n = idx - k * 768;
    float w = Wi[idx];
    __nv_bfloat16 h = __float2bfloat16(w);
    __nv_bfloat16 l = __float2bfloat16(w - __bfloat162float(h));
    g_wt_hi[n * 256 + k] = h;
    g_wt_lo[n * 256 + k] = l;
}

// ---------------------------------------------------------------------------
// Kernel 1: x_proj GEMM (unchanged from R6, known-good)
// ---------------------------------------------------------------------------
#define STAGE_B 40960
#define OFF_AHI 0
#define OFF_ALO 10240
#define OFF_BHI 20480
#define OFF_BLO 30720
#define XSMEM   (2 * STAGE_B)

__global__ void __launch_bounds__(256, 2)
xproj_mma_kernel(const float* __restrict__ bi)
{
    extern __shared__ char xsm[];
    const int tid = threadIdx.x, wid = tid >> 5, lane = tid & 31;
    const int warp_m = wid & 3, warp_n = wid >> 2;
    const int bN = blockIdx.x * 128;
    const int bM = blockIdx.y * 128;
    const uint32_t sb = smem_u32(xsm);

    const int grp = lane >> 3, r = lane & 7;
    uint32_t aoff[2], boff[4];
#pragma unroll
    for (int mt = 0; mt < 2; mt++)
        aoff[mt] = (uint32_t)((warp_m * 32 + mt * 16 + (grp & 1) * 8 + r) * 80
                              + (grp >> 1) * 16);
#pragma unroll
    for (int np = 0; np < 4; np++)
        boff[np] = (uint32_t)((warp_n * 64 + np * 16 + (grp >> 1) * 8 + r) * 80
                              + (grp & 1) * 16);

    const int c0row = tid >> 2, c0kc = tid & 3;
    const int c1row = (tid + 256) >> 2, c1kc = (tid + 256) & 3;

    auto load_stage = [&](int ks, int buf) {
        const uint32_t s = sb + buf * STAGE_B;
        const int k0 = ks * 32;
        {
            uint32_t so = c0row * 80 + c0kc * 16;
            size_t ga = (size_t)(bM + c0row) * 256 + k0 + c0kc * 8;
            size_t gb = (size_t)(bN + c0row) * 256 + k0 + c0kc * 8;
            cp16(s + OFF_AHI + so, g_a_hi + ga);
            cp16(s + OFF_ALO + so, g_a_lo + ga);
            cp16(s + OFF_BHI + so, g_wt_hi + gb);
            cp16(s + OFF_BLO + so, g_wt_lo + gb);
        }
        {
            uint32_t so = c1row * 80 + c1kc * 16;
            size_t ga = (size_t)(bM + c1row) * 256 + k0 + c1kc * 8;
            size_t gb = (size_t)(bN + c1row) * 256 + k0 + c1kc * 8;
            cp16(s + OFF_AHI + so, g_a_hi + ga);
            cp16(s + OFF_ALO + so, g_a_lo + ga);
            cp16(s + OFF_BHI + so, g_wt_hi + gb);
            cp16(s + OFF_BLO + so, g_wt_lo + gb);
        }
        asm volatile("cp.async.commit_group;" ::: "memory");
    };

    float acc[2][8][4];
#pragma unroll
    for (int mt = 0; mt < 2; mt++)
#pragma unroll
        for (int nt = 0; nt < 8; nt++)
#pragma unroll
            for (int e = 0; e < 4; e++) acc[mt][nt][e] = 0.f;

    load_stage(0, 0);
    load_stage(1, 1);

#pragma unroll 1
    for (int ks = 0; ks < 8; ks++) {
        if (ks < 7)
            asm volatile("cp.async.wait_group 1;" ::: "memory");
        else
            asm volatile("cp.async.wait_group 0;" ::: "memory");
        __syncthreads();

        const uint32_t s = sb + (ks & 1) * STAGE_B;
#pragma unroll
        for (int h = 0; h < 2; h++) {
            uint32_t a[2][2][4];
#pragma unroll
            for (int mt = 0; mt < 2; mt++) {
                LDSM4(a[0][mt], s + OFF_AHI + aoff[mt] + h * 32);
                LDSM4(a[1][mt], s + OFF_ALO + aoff[mt] + h * 32);
            }
#pragma unroll
            for (int np = 0; np < 4; np++) {
                uint32_t bh[4], bl[4];
                LDSM4(bh, s + OFF_BHI + boff[np] + h * 32);
                LDSM4(bl, s + OFF_BLO + boff[np] + h * 32);
#pragma unroll
                for (int mt = 0; mt < 2; mt++) {
                    MMA(acc[mt][2 * np],     a[0][mt], bh[0], bh[1]);
                    MMA(acc[mt][2 * np + 1], a[0][mt], bh[2], bh[3]);
                    MMA(acc[mt][2 * np],     a[0][mt], bl[0], bl[1]);
                    MMA(acc[mt][2 * np + 1], a[0][mt], bl[2], bl[3]);
                    MMA(acc[mt][2 * np],     a[1][mt], bh[0], bh[1]);
                    MMA(acc[mt][2 * np + 1], a[1][mt], bh[2], bh[3]);
                }
            }
        }
        __syncthreads();
        if (ks + 2 < 8) load_stage(ks + 2, ks & 1);
    }

    const int tq = lane >> 2, tr = lane & 3;
#pragma unroll
    for (int mt = 0; mt < 2; mt++) {
#pragma unroll
        for (int nt = 0; nt < 8; nt++) {
            int row = bM + warp_m * 32 + mt * 16 + tq;
            int col = bN + warp_n * 64 + nt * 8 + tr * 2;
            float2 bb = *(const float2*)(bi + col);
            float2 o0 = make_float2(acc[mt][nt][0] + bb.x, acc[mt][nt][1] + bb.y);
            float2 o1 = make_float2(acc[mt][nt][2] + bb.x, acc[mt][nt][3] + bb.y);
            *(float2*)(g_xproj + (size_t)row * 768 + col)       = o0;
            *(float2*)(g_xproj + (size_t)(row + 8) * 768 + col) = o1;
        }
    }
}

// ---------------------------------------------------------------------------
// Kernel 2: GRU scan R14 — stacked-A: rows 0-3 = h_hi (batches), rows 4-7 =
// h_lo. Per (chunk, gate): MMA(A, W_hi) + MMA(A, W_lo) — 96 MMA/warp (was
// 144); final value = D(row g) + D(row g+4) via shfl_down 16 (adds lo*lo,
// extra accuracy). Cluster 4, 256 threads, 8 fused full-K warps; B-hi in
// regs, B-lo LDSM2; GRU update fused in lanes 0-15; h broadcast hi@row g /
// lo@row g+4; barrier.cluster per step with x/done prefetch in the window.
// ---------------------------------------------------------------------------
#define SBP    528
#define SC_WHI 0
#define SC_WLO (192 * SBP)           // 101376
#define SC_A   (2 * 192 * SBP)       // 202752 ; A[phase][8 rows][SBP]
#define SC_APH (8 * SBP)             // 4224 per phase
#define SC_LO  (4 * SBP)             // lo rows offset within a phase
#define SC_SMEM (SC_A + 2 * SC_APH + 128)

__device__ __forceinline__ float fsigmoid(float x) {
    return __fdividef(1.f, 1.f + __expf(-x));
}
__device__ __forceinline__ float ftanh(float x) {
    return __fdividef(2.f, 1.f + __expf(-2.f * x)) - 1.f;
}

__global__ void __launch_bounds__(256, 1) __cluster_dims__(4, 1, 1)
scan_kernel(const void* __restrict__ done_raw,
            const float* __restrict__ init_h,
            const float* __restrict__ Wh_rz,
            const float* __restrict__ Wh_n,
            const float* __restrict__ bh_n,
            float* __restrict__ out)
{
    extern __shared__ char ssm[];
    const uint32_t sb = smem_u32(ssm);

    const int tid  = threadIdx.x;
    const int rank = blockIdx.x & 3;
    const int b0   = (blockIdx.x >> 2) * 4;

    const int done_mode = g_done_mode;
    const int* done_i32 = (const int*)done_raw;
    const unsigned char* done_u8 = (const unsigned char*)done_raw;

    // --- W slice -> bf16 hi/lo smem [192 n][256 k], pitch SBP ---
    for (int idx = tid; idx < 192 * 256; idx += 256) {
        int n = idx >> 8, k = idx & 255;
        int G = n >> 6, c = n & 63;
        float w = (G < 2) ? Wh_rz[(size_t)k * 512 + G * 256 + rank * 64 + c]
                          : Wh_n[(size_t)k * 256 + rank * 64 + c];
        __nv_bfloat16 hi = __float2bfloat16(w);
        __nv_bfloat16 lo = __float2bfloat16(w - __bfloat162float(hi));
        *(__nv_bfloat16*)(ssm + SC_WHI + n * SBP + k * 2) = hi;
        *(__nv_bfloat16*)(ssm + SC_WLO + n * SBP + k * 2) = lo;
    }
    __syncthreads();

    // --- identities ---
    const int w    = tid >> 5;        // warp 0..7: cols [8w, 8w+8)
    const int lane = tid & 31;
    const int g    = lane >> 2;       // D row for this lane (0-7)
    const int cp   = lane & 3;
    const int jg0  = rank * 64 + 8 * w + 2 * cp;
    const bool is_ew = (lane < 16);   // rows 0-3 = batches

    // B-hi fragments -> registers: 3 gates x 16 chunks x 2 regs
    uint32_t bhreg[3][16][2];
    {
        const int nrow = lane >> 2, kb = (lane & 3) * 4;
#pragma unroll
        for (int G = 0; G < 3; G++) {
            const uint32_t base = (uint32_t)((G * 64 + 8 * w + nrow) * SBP);
#pragma unroll
            for (int c = 0; c < 16; c++) {
                bhreg[G][c][0] = *(const uint32_t*)(ssm + SC_WHI + base + c * 32 + kb);
                bhreg[G][c][1] = *(const uint32_t*)(ssm + SC_WHI + base + c * 32 + kb + 16);
            }
        }
    }

    // ldmatrix lane bases
    const uint32_t a_lane = (uint32_t)((lane & 7) * SBP + ((lane >> 3) & 1) * 16);
    uint32_t bl2[3];
#pragma unroll
    for (int G = 0; G < 3; G++)
        bl2[G] = sb + SC_WLO
            + (uint32_t)((G * 64 + 8 * w + (lane & 7)) * SBP + ((lane >> 3) & 1) * 16);

    // --- per-lane state (ew lanes) ---
    const float2 bb = is_ew ? *(const float2*)(bh_n + jg0) : make_float2(0.f, 0.f);
    const float* xbase = g_xproj + (size_t)(b0 + g) * Tsz * 768 + jg0;
    const size_t done_base = (size_t)(b0 + g) * Tsz;

    float hcur0 = 0.f, hcur1 = 0.f;
    float2 pxr = make_float2(0.f, 0.f), pxz = pxr, pxn = pxr;
    int dn_next = 0;

    if (is_ew) {
        int d0 = done_mode ? (int)done_u8[done_base] : done_i32[done_base];
        float2 h0 = *(const float2*)(init_h + (size_t)(b0 + g) * Hsz + jg0);
        hcur0 = d0 ? 0.f : h0.x;
        hcur1 = d0 ? 0.f : h0.y;
        __nv_bfloat16 ha = __float2bfloat16(hcur0);
        __nv_bfloat16 hb = __float2bfloat16(hcur1);
        __nv_bfloat16 la = __float2bfloat16(hcur0 - __bfloat162float(ha));
        __nv_bfloat16 lb = __float2bfloat16(hcur1 - __bfloat162float(hb));
        uint32_t hp = (uint32_t)__bfloat16_as_ushort(ha)
                    | ((uint32_t)__bfloat16_as_ushort(hb) << 16);
        uint32_t lp = (uint32_t)__bfloat16_as_ushort(la)
                    | ((uint32_t)__bfloat16_as_ushort(lb) << 16);
        uint32_t laddr = sb + SC_A + (uint32_t)(g * SBP + jg0 * 2);
#pragma unroll
        for (uint32_t dst = 0; dst < 4; dst++) {
            uint32_t ra;
            asm volatile("mapa.shared::cluster.u32 %0, %1, %2;"
                         : "=r"(ra) : "r"(laddr), "r"(dst));
            asm volatile("st.shared::cluster.u32 [%0], %1;" :: "r"(ra), "r"(hp) : "memory");
            asm volatile("st.shared::cluster.u32 [%0], %1;"
                         :: "r"(ra + SC_LO), "r"(lp) : "memory");
        }
        pxr = *(const float2*)(xbase);
        pxz = *(const float2*)(xbase + 256);
        pxn = *(const float2*)(xbase + 512);
        dn_next = done_mode ? (int)done_u8[done_base + 1] : done_i32[done_base + 1];
    }
    __syncthreads();
    asm volatile("barrier.cluster.arrive.aligned;" ::: "memory");
    asm volatile("barrier.cluster.wait.aligned;" ::: "memory");

    float* ys = out + Bsz * Hsz;
    int p = 0;

    for (int t = 0; t < Tsz; t++) {
        // ---- mma: 3 gates x 16 chunks x 2 products, 6 acc chains ----
        float cg[3][2][4];
#pragma unroll
        for (int G = 0; G < 3; G++)
#pragma unroll
            for (int s = 0; s < 2; s++)
#pragma unroll
                for (int e = 0; e < 4; e++) cg[G][s][e] = 0.f;

        const uint32_t a_base = sb + SC_A + p * SC_APH + a_lane;
#pragma unroll
        for (int c = 0; c < 16; c++) {
            const uint32_t co = (uint32_t)(c * 32);
            uint32_t a0r, a1r;
            LDSM2(a0r, a1r, a_base + co);
            uint32_t b0r, b1r, b2r, b3r, b4r, b5r;
            LDSM2(b0r, b1r, bl2[0] + co);
            LDSM2(b2r, b3r, bl2[1] + co);
            LDSM2(b4r, b5r, bl2[2] + co);
            const int s = c & 1;
            MMA_DUP(cg[0][s], a0r, a1r, bhreg[0][c][0], bhreg[0][c][1]);
            MMA_DUP(cg[1][s], a0r, a1r, bhreg[1][c][0], bhreg[1][c][1]);
            MMA_DUP(cg[2][s], a0r, a1r, bhreg[2][c][0], bhreg[2][c][1]);
            MMA_DUP(cg[0][s], a0r, a1r, b0r, b1r);
            MMA_DUP(cg[1][s], a0r, a1r, b2r, b3r);
            MMA_DUP(cg[2][s], a0r, a1r, b4r, b5r);
        }

        // ---- hi/lo row reduction via shfl (all lanes participate) ----
        float sr0 = cg[0][0][0] + cg[0][1][0], sr1 = cg[0][0][1] + cg[0][1][1];
        float sz0 = cg[1][0][0] + cg[1][1][0], sz1 = cg[1][0][1] + cg[1][1][1];
        float sn0 = cg[2][0][0] + cg[2][1][0], sn1 = cg[2][0][1] + cg[2][1][1];
        float hr0 = sr0 + __shfl_down_sync(0xffffffffu, sr0, 16);
        float hr1 = sr1 + __shfl_down_sync(0xffffffffu, sr1, 16);
        float hz0 = sz0 + __shfl_down_sync(0xffffffffu, sz0, 16);
        float hz1 = sz1 + __shfl_down_sync(0xffffffffu, sz1, 16);
        float hn0 = sn0 + __shfl_down_sync(0xffffffffu, sn0, 16);
        float hn1 = sn1 + __shfl_down_sync(0xffffffffu, sn1, 16);

        // ---- fused elementwise (lanes 0-15) ----
        if (is_ew) {
            float r0 = fsigmoid(pxr.x + hr0);
            float r1 = fsigmoid(pxr.y + hr1);
            float z0 = fsigmoid(pxz.x + hz0);
            float z1 = fsigmoid(pxz.y + hz1);
            float n0 = ftanh(pxn.x + r0 * (hn0 + bb.x));
            float n1 = ftanh(pxn.y + r1 * (hn1 + bb.y));
            float hnew0 = n0 + z0 * (hcur0 - n0);
            float hnew1 = n1 + z1 * (hcur1 - n1);

            *(float2*)(ys + ((size_t)(b0 + g) * Tsz + t) * Hsz + jg0)
                = make_float2(hnew0, hnew1);
            if (t == Tsz - 1)
                *(float2*)(out + (size_t)(b0 + g) * Hsz + jg0)
                    = make_float2(hnew0, hnew1);

            float hw0 = dn_next ? 0.f : hnew0;
            float hw1 = dn_next ? 0.f : hnew1;
            hcur0 = hw0;
            hcur1 = hw1;
            __nv_bfloat16 ha = __float2bfloat16(hw0);
            __nv_bfloat16 hb = __float2bfloat16(hw1);
            __nv_bfloat16 la = __float2bfloat16(hw0 - __bfloat162float(ha));
            __nv_bfloat16 lb = __float2bfloat16(hw1 - __bfloat162float(hb));
            uint32_t hp = (uint32_t)__bfloat16_as_ushort(ha)
                        | ((uint32_t)__bfloat16_as_ushort(hb) << 16);
            uint32_t lp = (uint32_t)__bfloat16_as_ushort(la)
                        | ((uint32_t)__bfloat16_as_ushort(lb) << 16);
            uint32_t laddr = sb + SC_A + (uint32_t)((1 - p) * SC_APH + g * SBP + jg0 * 2);
#pragma unroll
            for (uint32_t dst = 0; dst < 4; dst++) {
                uint32_t ra;
                asm volatile("mapa.shared::cluster.u32 %0, %1, %2;"
                             : "=r"(ra) : "r"(laddr), "r"(dst));
                asm volatile("st.shared::cluster.u32 [%0], %1;"
                             :: "r"(ra), "r"(hp) : "memory");
                asm volatile("st.shared::cluster.u32 [%0], %1;"
                             :: "r"(ra + SC_LO), "r"(lp) : "memory");
            }
        }

        asm volatile("barrier.cluster.arrive.aligned;" ::: "memory");
        if (is_ew && t + 1 < Tsz) {
            const float* xp = xbase + (size_t)(t + 1) * 768;
            pxr = *(const float2*)(xp);
            pxz = *(const float2*)(xp + 256);
            pxn = *(const float2*)(xp + 512);
            if (t + 2 < Tsz) {
                size_t di = done_base + t + 2;
                dn_next = done_mode ? (int)done_u8[di] : done_i32[di];
            } else {
                dn_next = 0;
            }
        }
        asm volatile("barrier.cluster.wait.aligned;" ::: "memory");
        p ^= 1;
    }
}

// ---------------------------------------------------------------------------
// Launch
// ---------------------------------------------------------------------------
extern "C" void kernel_launch(void* const* d_in, const int* in_sizes, int n_in,
                              void* d_out, int out_size)
{
    (void)in_sizes; (void)n_in; (void)out_size;
    const float* obs    = (const float*)d_in[0];
    const void*  done   = d_in[1];
    const float* init_h = (const float*)d_in[2];
    const float* Wi     = (const float*)d_in[3];
    const float* bi     = (const float*)d_in[4];
    const float* Wh_rz  = (const float*)d_in[5];
    const float* Wh_n   = (const float*)d_in[6];
    const float* bh_n   = (const float*)d_in[7];
    float* out = (float*)d_out;

    cudaFuncSetAttribute(scan_kernel, cudaFuncAttributeMaxDynamicSharedMemorySize,
                         SC_SMEM);
    cudaFuncSetAttribute(xproj_mma_kernel, cudaFuncAttributeMaxDynamicSharedMemorySize,
                         XSMEM);

    detect_done_kernel<<<128, 256>>>((const unsigned int*)done);
    decompose_obs<<<32768, 256>>>(obs);
    decompose_wi<<<768, 256>>>(Wi);

    dim3 ggrid(6, 1024);
    xproj_mma_kernel<<<ggrid, 256, XSMEM>>>(bi);

    scan_kernel<<<128, 256, SC_SMEM>>>(done, init_h, Wh_rz, Wh_n, bh_n, out);
}

// round 15
// speedup vs baseline: 1.4726x; 1.4726x over previous
#include <cuda_runtime.h>
#include <cuda_bf16.h>
#include <cstdint>

#define Bsz 128
#define Tsz 1024
#define Dsz 256
#define Hsz 256

typedef unsigned long long u64;

// ---------------- scratch ----------
__device__ float g_xproj[(size_t)Bsz * Tsz * 3 * Hsz];
__device__ __nv_bfloat16 g_a_hi[(size_t)Bsz * Tsz * Dsz];
__device__ __nv_bfloat16 g_a_lo[(size_t)Bsz * Tsz * Dsz];
__device__ __nv_bfloat16 g_wt_hi[768 * 256];
__device__ __nv_bfloat16 g_wt_lo[768 * 256];
__device__ int g_done_mode;

__device__ __forceinline__ uint32_t smem_u32(const void* p) {
    uint32_t a;
    asm("{ .reg .u64 t; cvta.to.shared.u64 t, %1; cvt.u32.u64 %0, t; }"
        : "=r"(a) : "l"(p));
    return a;
}
__device__ __forceinline__ void cp16(uint32_t s, const void* g) {
    asm volatile("cp.async.cg.shared.global [%0], [%1], 16;"
                 :: "r"(s), "l"(__cvta_generic_to_global(g)) : "memory");
}
#define LDSM4(r, addr) \
    asm volatile("ldmatrix.sync.aligned.m8n8.x4.shared.b16 {%0,%1,%2,%3}, [%4];" \
                 : "=r"((r)[0]), "=r"((r)[1]), "=r"((r)[2]), "=r"((r)[3]) : "r"(addr))
#define LDSM2(r0, r1, addr) \
    asm volatile("ldmatrix.sync.aligned.m8n8.x2.shared.b16 {%0,%1}, [%2];" \
                 : "=r"(r0), "=r"(r1) : "r"(addr))
#define MMA(c, A, b0, b1) \
    asm volatile("mma.sync.aligned.m16n8k16.row.col.f32.bf16.bf16.f32 " \
                 "{%0,%1,%2,%3},{%4,%5,%6,%7},{%8,%9},{%0,%1,%2,%3};" \
                 : "+f"((c)[0]), "+f"((c)[1]), "+f"((c)[2]), "+f"((c)[3]) \
                 : "r"((A)[0]), "r"((A)[1]), "r"((A)[2]), "r"((A)[3]), \
                   "r"(b0), "r"(b1))
// A rows 8-15 duplicate rows 0-7 (D rows 8-15 = dup, ignored); a0=k0-7, a1=k8-15
#define MMA_DUP(c, a0, a1, b0, b1) \
    asm volatile("mma.sync.aligned.m16n8k16.row.col.f32.bf16.bf16.f32 " \
                 "{%0,%1,%2,%3},{%4,%5,%6,%7},{%8,%9},{%0,%1,%2,%3};" \
                 : "+f"((c)[0]), "+f"((c)[1]), "+f"((c)[2]), "+f"((c)[3]) \
                 : "r"(a0), "r"(a0), "r"(a1), "r"(a1), "r"(b0), "r"(b1))

// ---------------------------------------------------------------------------
__global__ void detect_done_kernel(const unsigned int* __restrict__ done_words)
{
    int i = blockIdx.x * blockDim.x + threadIdx.x;
    if (done_words[i] > 1u) atomicOr(&g_done_mode, 1);
}

__global__ void decompose_obs(const float* __restrict__ src)
{
    size_t i = (size_t)blockIdx.x * blockDim.x + threadIdx.x;
    float4 v = ((const float4*)src)[i];
    __nv_bfloat16 h0 = __float2bfloat16(v.x);
    __nv_bfloat16 h1 = __float2bfloat16(v.y);
    __nv_bfloat16 h2 = __float2bfloat16(v.z);
    __nv_bfloat16 h3 = __float2bfloat16(v.w);
    __nv_bfloat16 l0 = __float2bfloat16(v.x - __bfloat162float(h0));
    __nv_bfloat16 l1 = __float2bfloat16(v.y - __bfloat162float(h1));
    __nv_bfloat16 l2 = __float2bfloat16(v.z - __bfloat162float(h2));
    __nv_bfloat16 l3 = __float2bfloat16(v.w - __bfloat162float(h3));
    __nv_bfloat162* hp = (__nv_bfloat162*)g_a_hi;
    __nv_bfloat162* lp = (__nv_bfloat162*)g_a_lo;
    hp[2 * i]     = __nv_bfloat162(h0, h1);
    hp[2 * i + 1] = __nv_bfloat162(h2, h3);
    lp[2 * i]     = __nv_bfloat162(l0, l1);
    lp[2 * i + 1] = __nv_bfloat162(l2, l3);
}

__global__ void decompose_wi(const float* __restrict__ Wi)
{
    int idx = blockIdx.x * blockDim.x + threadIdx.x;
    int k = idx / 768, n = idx - k * 768;
    float w = Wi[idx];
    __nv_bfloat16 h = __float2bfloat16(w);
    __nv_bfloat16 l = __float2bfloat16(w - __bfloat162float(h));
    g_wt_hi[n * 256 + k] = h;
    g_wt_lo[n * 256 + k] = l;
}

// ---------------------------------------------------------------------------
// Kernel 1: x_proj GEMM (unchanged from R6, known-good)
// ---------------------------------------------------------------------------
#define STAGE_B 40960
#define OFF_AHI 0
#define OFF_ALO 10240
#define OFF_BHI 20480
#define OFF_BLO 30720
#define XSMEM   (2 * STAGE_B)

__global__ void __launch_bounds__(256, 2)
xproj_mma_kernel(const float* __restrict__ bi)
{
    extern __shared__ char xsm[];
    const int tid = threadIdx.x, wid = tid >> 5, lane = tid & 31;
    const int warp_m = wid & 3, warp_n = wid >> 2;
    const int bN = blockIdx.x * 128;
    const int bM = blockIdx.y * 128;
    const uint32_t sb = smem_u32(xsm);

    const int grp = lane >> 3, r = lane & 7;
    uint32_t aoff[2], boff[4];
#pragma unroll
    for (int mt = 0; mt < 2; mt++)
        aoff[mt] = (uint32_t)((warp_m * 32 + mt * 16 + (grp & 1) * 8 + r) * 80
                              + (grp >> 1) * 16);
#pragma unroll
    for (int np = 0; np < 4; np++)
        boff[np] = (uint32_t)((warp_n * 64 + np * 16 + (grp >> 1) * 8 + r) * 80
                              + (grp & 1) * 16);

    const int c0row = tid >> 2, c0kc = tid & 3;
    const int c1row = (tid + 256) >> 2, c1kc = (tid + 256) & 3;

    auto load_stage = [&](int ks, int buf) {
        const uint32_t s = sb + buf * STAGE_B;
        const int k0 = ks * 32;
        {
            uint32_t so = c0row * 80 + c0kc * 16;
            size_t ga = (size_t)(bM + c0row) * 256 + k0 + c0kc * 8;
            size_t gb = (size_t)(bN + c0row) * 256 + k0 + c0kc * 8;
            cp16(s + OFF_AHI + so, g_a_hi + ga);
            cp16(s + OFF_ALO + so, g_a_lo + ga);
            cp16(s + OFF_BHI + so, g_wt_hi + gb);
            cp16(s + OFF_BLO + so, g_wt_lo + gb);
        }
        {
            uint32_t so = c1row * 80 + c1kc * 16;
            size_t ga = (size_t)(bM + c1row) * 256 + k0 + c1kc * 8;
            size_t gb = (size_t)(bN + c1row) * 256 + k0 + c1kc * 8;
            cp16(s + OFF_AHI + so, g_a_hi + ga);
            cp16(s + OFF_ALO + so, g_a_lo + ga);
            cp16(s + OFF_BHI + so, g_wt_hi + gb);
            cp16(s + OFF_BLO + so, g_wt_lo + gb);
        }
        asm volatile("cp.async.commit_group;" ::: "memory");
    };

    float acc[2][8][4];
#pragma unroll
    for (int mt = 0; mt < 2; mt++)
#pragma unroll
        for (int nt = 0; nt < 8; nt++)
#pragma unroll
            for (int e = 0; e < 4; e++) acc[mt][nt][e] = 0.f;

    load_stage(0, 0);
    load_stage(1, 1);

#pragma unroll 1
    for (int ks = 0; ks < 8; ks++) {
        if (ks < 7)
            asm volatile("cp.async.wait_group 1;" ::: "memory");
        else
            asm volatile("cp.async.wait_group 0;" ::: "memory");
        __syncthreads();

        const uint32_t s = sb + (ks & 1) * STAGE_B;
#pragma unroll
        for (int h = 0; h < 2; h++) {
            uint32_t a[2][2][4];
#pragma unroll
            for (int mt = 0; mt < 2; mt++) {
                LDSM4(a[0][mt], s + OFF_AHI + aoff[mt] + h * 32);
                LDSM4(a[1][mt], s + OFF_ALO + aoff[mt] + h * 32);
            }
#pragma unroll
            for (int np = 0; np < 4; np++) {
                uint32_t bh[4], bl[4];
                LDSM4(bh, s + OFF_BHI + boff[np] + h * 32);
                LDSM4(bl, s + OFF_BLO + boff[np] + h * 32);
#pragma unroll
                for (int mt = 0; mt < 2; mt++) {
                    MMA(acc[mt][2 * np],     a[0][mt], bh[0], bh[1]);
                    MMA(acc[mt][2 * np + 1], a[0][mt], bh[2], bh[3]);
                    MMA(acc[mt][2 * np],     a[0][mt], bl[0], bl[1]);
                    MMA(acc[mt][2 * np + 1], a[0][mt], bl[2], bl[3]);
                    MMA(acc[mt][2 * np],     a[1][mt], bh[0], bh[1]);
                    MMA(acc[mt][2 * np + 1], a[1][mt], bh[2], bh[3]);
                }
            }
        }
        __syncthreads();
        if (ks + 2 < 8) load_stage(ks + 2, ks & 1);
    }

    const int tq = lane >> 2, tr = lane & 3;
#pragma unroll
    for (int mt = 0; mt < 2; mt++) {
#pragma unroll
        for (int nt = 0; nt < 8; nt++) {
            int row = bM + warp_m * 32 + mt * 16 + tq;
            int col = bN + warp_n * 64 + nt * 8 + tr * 2;
            float2 bb = *(const float2*)(bi + col);
            float2 o0 = make_float2(acc[mt][nt][0] + bb.x, acc[mt][nt][1] + bb.y);
            float2 o1 = make_float2(acc[mt][nt][2] + bb.x, acc[mt][nt][3] + bb.y);
            *(float2*)(g_xproj + (size_t)row * 768 + col)       = o0;
            *(float2*)(g_xproj + (size_t)(row + 8) * 768 + col) = o1;
        }
    }
}

// ---------------------------------------------------------------------------
// Kernel 2: GRU scan R14 (re-bench, byte-identical) — stacked-A: rows 0-3 =
// h_hi (batches), rows 4-7 = h_lo. Per (chunk, gate): MMA(A,W_hi)+MMA(A,W_lo)
// = 96 MMA/warp; value = D(row g) + D(row g+4) via shfl_down 16. Cluster 4,
// 256 threads, 8 fused full-K warps; B-hi in regs, B-lo LDSM2; GRU update
// fused in lanes 0-15; h broadcast hi@row g / lo@row g+4; barrier.cluster
// per step with x/done prefetch in the window.
// ---------------------------------------------------------------------------
#define SBP    528
#define SC_WHI 0
#define SC_WLO (192 * SBP)           // 101376
#define SC_A   (2 * 192 * SBP)       // 202752 ; A[phase][8 rows][SBP]
#define SC_APH (8 * SBP)             // 4224 per phase
#define SC_LO  (4 * SBP)             // lo rows offset within a phase
#define SC_SMEM (SC_A + 2 * SC_APH + 128)

__device__ __forceinline__ float fsigmoid(float x) {
    return __fdividef(1.f, 1.f + __expf(-x));
}
__device__ __forceinline__ float ftanh(float x) {
    return __fdividef(2.f, 1.f + __expf(-2.f * x)) - 1.f;
}

__global__ void __launch_bounds__(256, 1) __cluster_dims__(4, 1, 1)
scan_kernel(const void* __restrict__ done_raw,
            const float* __restrict__ init_h,
            const float* __restrict__ Wh_rz,
            const float* __restrict__ Wh_n,
            const float* __restrict__ bh_n,
            float* __restrict__ out)
{
    extern __shared__ char ssm[];
    const uint32_t sb = smem_u32(ssm);

    const int tid  = threadIdx.x;
    const int rank = blockIdx.x & 3;
    const int b0   = (blockIdx.x >> 2) * 4;

    const int done_mode = g_done_mode;
    const int* done_i32 = (const int*)done_raw;
    const unsigned char* done_u8 = (const unsigned char*)done_raw;

    // --- W slice -> bf16 hi/lo smem [192 n][256 k], pitch SBP ---
    for (int idx = tid; idx < 192 * 256; idx += 256) {
        int n = idx >> 8, k = idx & 255;
        int G = n >> 6, c = n & 63;
        float w = (G < 2) ? Wh_rz[(size_t)k * 512 + G * 256 + rank * 64 + c]
                          : Wh_n[(size_t)k * 256 + rank * 64 + c];
        __nv_bfloat16 hi = __float2bfloat16(w);
        __nv_bfloat16 lo = __float2bfloat16(w - __bfloat162float(hi));
        *(__nv_bfloat16*)(ssm + SC_WHI + n * SBP + k * 2) = hi;
        *(__nv_bfloat16*)(ssm + SC_WLO + n * SBP + k * 2) = lo;
    }
    __syncthreads();

    // --- identities ---
    const int w    = tid >> 5;        // warp 0..7: cols [8w, 8w+8)
    const int lane = tid & 31;
    const int g    = lane >> 2;       // D row for this lane (0-7)
    const int cp   = lane & 3;
    const int jg0  = rank * 64 + 8 * w + 2 * cp;
    const bool is_ew = (lane < 16);   // rows 0-3 = batches

    // B-hi fragments -> registers: 3 gates x 16 chunks x 2 regs
    uint32_t bhreg[3][16][2];
    {
        const int nrow = lane >> 2, kb = (lane & 3) * 4;
#pragma unroll
        for (int G = 0; G < 3; G++) {
            const uint32_t base = (uint32_t)((G * 64 + 8 * w + nrow) * SBP);
#pragma unroll
            for (int c = 0; c < 16; c++) {
                bhreg[G][c][0] = *(const uint32_t*)(ssm + SC_WHI + base + c * 32 + kb);
                bhreg[G][c][1] = *(const uint32_t*)(ssm + SC_WHI + base + c * 32 + kb + 16);
            }
        }
    }

    // ldmatrix lane bases
    const uint32_t a_lane = (uint32_t)((lane & 7) * SBP + ((lane >> 3) & 1) * 16);
    uint32_t bl2[3];
#pragma unroll
    for (int G = 0; G < 3; G++)
        bl2[G] = sb + SC_WLO
            + (uint32_t)((G * 64 + 8 * w + (lane & 7)) * SBP + ((lane >> 3) & 1) * 16);

    // --- per-lane state (ew lanes) ---
    const float2 bb = is_ew ? *(const float2*)(bh_n + jg0) : make_float2(0.f, 0.f);
    const float* xbase = g_xproj + (size_t)(b0 + g) * Tsz * 768 + jg0;
    const size_t done_base = (size_t)(b0 + g) * Tsz;

    float hcur0 = 0.f, hcur1 = 0.f;
    float2 pxr = make_float2(0.f, 0.f), pxz = pxr, pxn = pxr;
    int dn_next = 0;

    if (is_ew) {
        int d0 = done_mode ? (int)done_u8[done_base] : done_i32[done_base];
        float2 h0 = *(const float2*)(init_h + (size_t)(b0 + g) * Hsz + jg0);
        hcur0 = d0 ? 0.f : h0.x;
        hcur1 = d0 ? 0.f : h0.y;
        __nv_bfloat16 ha = __float2bfloat16(hcur0);
        __nv_bfloat16 hb = __float2bfloat16(hcur1);
        __nv_bfloat16 la = __float2bfloat16(hcur0 - __bfloat162float(ha));
        __nv_bfloat16 lb = __float2bfloat16(hcur1 - __bfloat162float(hb));
        uint32_t hp = (uint32_t)__bfloat16_as_ushort(ha)
                    | ((uint32_t)__bfloat16_as_ushort(hb) << 16);
        uint32_t lp = (uint32_t)__bfloat16_as_ushort(la)
                    | ((uint32_t)__bfloat16_as_ushort(lb) << 16);
        uint32_t laddr = sb + SC_A + (uint32_t)(g * SBP + jg0 * 2);
#pragma unroll
        for (uint32_t dst = 0; dst < 4; dst++) {
            uint32_t ra;
            asm volatile("mapa.shared::cluster.u32 %0, %1, %2;"
                         : "=r"(ra) : "r"(laddr), "r"(dst));
            asm volatile("st.shared::cluster.u32 [%0], %1;" :: "r"(ra), "r"(hp) : "memory");
            asm volatile("st.shared::cluster.u32 [%0], %1;"
                         :: "r"(ra + SC_LO), "r"(lp) : "memory");
        }
        pxr = *(const float2*)(xbase);
        pxz = *(const float2*)(xbase + 256);
        pxn = *(const float2*)(xbase + 512);
        dn_next = done_mode ? (int)done_u8[done_base + 1] : done_i32[done_base + 1];
    }
    __syncthreads();
    asm volatile("barrier.cluster.arrive.aligned;" ::: "memory");
    asm volatile("barrier.cluster.wait.aligned;" ::: "memory");

    float* ys = out + Bsz * Hsz;
    int p = 0;

    for (int t = 0; t < Tsz; t++) {
        // ---- mma: 3 gates x 16 chunks x 2 products, 6 acc chains ----
        float cg[3][2][4];
#pragma unroll
        for (int G = 0; G < 3; G++)
#pragma unroll
            for (int s = 0; s < 2; s++)
#pragma unroll
                for (int e = 0; e < 4; e++) cg[G][s][e] = 0.f;

        const uint32_t a_base = sb + SC_A + p * SC_APH + a_lane;
#pragma unroll
        for (int c = 0; c < 16; c++) {
            const uint32_t co = (uint32_t)(c * 32);
            uint32_t a0r, a1r;
            LDSM2(a0r, a1r, a_base + co);
            uint32_t b0r, b1r, b2r, b3r, b4r, b5r;
            LDSM2(b0r, b1r, bl2[0] + co);
            LDSM2(b2r, b3r, bl2[1] + co);
            LDSM2(b4r, b5r, bl2[2] + co);
            const int s = c & 1;
            MMA_DUP(cg[0][s], a0r, a1r, bhreg[0][c][0], bhreg[0][c][1]);
            MMA_DUP(cg[1][s], a0r, a1r, bhreg[1][c][0], bhreg[1][c][1]);
            MMA_DUP(cg[2][s], a0r, a1r, bhreg[2][c][0], bhreg[2][c][1]);
            MMA_DUP(cg[0][s], a0r, a1r, b0r, b1r);
            MMA_DUP(cg[1][s], a0r, a1r, b2r, b3r);
            MMA_DUP(cg[2][s], a0r, a1r, b4r, b5r);
        }

        // ---- hi/lo row reduction via shfl (all lanes participate) ----
        float sr0 = cg[0][0][0] + cg[0][1][0], sr1 = cg[0][0][1] + cg[0][1][1];
        float sz0 = cg[1][0][0] + cg[1][1][0], sz1 = cg[1][0][1] + cg[1][1][1];
        float sn0 = cg[2][0][0] + cg[2][1][0], sn1 = cg[2][0][1] + cg[2][1][1];
        float hr0 = sr0 + __shfl_down_sync(0xffffffffu, sr0, 16);
        float hr1 = sr1 + __shfl_down_sync(0xffffffffu, sr1, 16);
        float hz0 = sz0 + __shfl_down_sync(0xffffffffu, sz0, 16);
        float hz1 = sz1 + __shfl_down_sync(0xffffffffu, sz1, 16);
        float hn0 = sn0 + __shfl_down_sync(0xffffffffu, sn0, 16);
        float hn1 = sn1 + __shfl_down_sync(0xffffffffu, sn1, 16);

        // ---- fused elementwise (lanes 0-15) ----
        if (is_ew) {
            float r0 = fsigmoid(pxr.x + hr0);
            float r1 = fsigmoid(pxr.y + hr1);
            float z0 = fsigmoid(pxz.x + hz0);
            float z1 = fsigmoid(pxz.y + hz1);
            float n0 = ftanh(pxn.x + r0 * (hn0 + bb.x));
            float n1 = ftanh(pxn.y + r1 * (hn1 + bb.y));
            float hnew0 = n0 + z0 * (hcur0 - n0);
            float hnew1 = n1 + z1 * (hcur1 - n1);

            *(float2*)(ys + ((size_t)(b0 + g) * Tsz + t) * Hsz + jg0)
                = make_float2(hnew0, hnew1);
            if (t == Tsz - 1)
                *(float2*)(out + (size_t)(b0 + g) * Hsz + jg0)
                    = make_float2(hnew0, hnew1);

            float hw0 = dn_next ? 0.f : hnew0;
            float hw1 = dn_next ? 0.f : hnew1;
            hcur0 = hw0;
            hcur1 = hw1;
            __nv_bfloat16 ha = __float2bfloat16(hw0);
            __nv_bfloat16 hb = __float2bfloat16(hw1);
            __nv_bfloat16 la = __float2bfloat16(hw0 - __bfloat162float(ha));
            __nv_bfloat16 lb = __float2bfloat16(hw1 - __bfloat162float(hb));
            uint32_t hp = (uint32_t)__bfloat16_as_ushort(ha)
                        | ((uint32_t)__bfloat16_as_ushort(hb) << 16);
            uint32_t lp = (uint32_t)__bfloat16_as_ushort(la)
                        | ((uint32_t)__bfloat16_as_ushort(lb) << 16);
            uint32_t laddr = sb + SC_A + (uint32_t)((1 - p) * SC_APH + g * SBP + jg0 * 2);
#pragma unroll
            for (uint32_t dst = 0; dst < 4; dst++) {
                uint32_t ra;
                asm volatile("mapa.shared::cluster.u32 %0, %1, %2;"
                             : "=r"(ra) : "r"(laddr), "r"(dst));
                asm volatile("st.shared::cluster.u32 [%0], %1;"
                             :: "r"(ra), "r"(hp) : "memory");
                asm volatile("st.shared::cluster.u32 [%0], %1;"
                             :: "r"(ra + SC_LO), "r"(lp) : "memory");
            }
        }

        asm volatile("barrier.cluster.arrive.aligned;" ::: "memory");
        if (is_ew && t + 1 < Tsz) {
            const float* xp = xbase + (size_t)(t + 1) * 768;
            pxr = *(const float2*)(xp);
            pxz = *(const float2*)(xp + 256);
            pxn = *(const float2*)(xp + 512);
            if (t + 2 < Tsz) {
                size_t di = done_base + t + 2;
                dn_next = done_mode ? (int)done_u8[di] : done_i32[di];
            } else {
                dn_next = 0;
            }
        }
        asm volatile("barrier.cluster.wait.aligned;" ::: "memory");
        p ^= 1;
    }
}

// ---------------------------------------------------------------------------
// Launch
// ---------------------------------------------------------------------------
extern "C" void kernel_launch(void* const* d_in, const int* in_sizes, int n_in,
                              void* d_out, int out_size)
{
    (void)in_sizes; (void)n_in; (void)out_size;
    const float* obs    = (const float*)d_in[0];
    const void*  done   = d_in[1];
    const float* init_h = (const float*)d_in[2];
    const float* Wi     = (const float*)d_in[3];
    const float* bi     = (const float*)d_in[4];
    const float* Wh_rz  = (const float*)d_in[5];
    const float* Wh_n   = (const float*)d_in[6];
    const float* bh_n   = (const float*)d_in[7];
    float* out = (float*)d_out;

    cudaFuncSetAttribute(scan_kernel, cudaFuncAttributeMaxDynamicSharedMemorySize,
                         SC_SMEM);
    cudaFuncSetAttribute(xproj_mma_kernel, cudaFuncAttributeMaxDynamicSharedMemorySize,
                         XSMEM);

    detect_done_kernel<<<128, 256>>>((const unsigned int*)done);
    decompose_obs<<<32768, 256>>>(obs);
    decompose_wi<<<768, 256>>>(Wi);

    dim3 ggrid(6, 1024);
    xproj_mma_kernel<<<ggrid, 256, XSMEM>>>(bi);

    scan_kernel<<<128, 256, SC_SMEM>>>(done, init_h, Wh_rz, Wh_n, bh_n, out);
}

// round 16
// speedup vs baseline: 1.6337x; 1.1094x over previous
#include <cuda_runtime.h>
#include <cuda_bf16.h>
#include <cstdint>

#define Bsz 128
#define Tsz 1024
#define Dsz 256
#define Hsz 256

typedef unsigned long long u64;

// ---------------- scratch ----------
__device__ float g_xproj[(size_t)Bsz * Tsz * 3 * Hsz];
__device__ __nv_bfloat16 g_a_hi[(size_t)Bsz * Tsz * Dsz];
__device__ __nv_bfloat16 g_a_lo[(size_t)Bsz * Tsz * Dsz];
__device__ __nv_bfloat16 g_wt_hi[768 * 256];
__device__ __nv_bfloat16 g_wt_lo[768 * 256];
__device__ int g_done_mode;

__device__ __forceinline__ uint32_t smem_u32(const void* p) {
    uint32_t a;
    asm("{ .reg .u64 t; cvta.to.shared.u64 t, %1; cvt.u32.u64 %0, t; }"
        : "=r"(a) : "l"(p));
    return a;
}
__device__ __forceinline__ void cp16(uint32_t s, const void* g) {
    asm volatile("cp.async.cg.shared.global [%0], [%1], 16;"
                 :: "r"(s), "l"(__cvta_generic_to_global(g)) : "memory");
}
#define LDSM4(r, addr) \
    asm volatile("ldmatrix.sync.aligned.m8n8.x4.shared.b16 {%0,%1,%2,%3}, [%4];" \
                 : "=r"((r)[0]), "=r"((r)[1]), "=r"((r)[2]), "=r"((r)[3]) : "r"(addr))
#define LDSM2(r0, r1, addr) \
    asm volatile("ldmatrix.sync.aligned.m8n8.x2.shared.b16 {%0,%1}, [%2];" \
                 : "=r"(r0), "=r"(r1) : "r"(addr))
#define MMA(c, A, b0, b1) \
    asm volatile("mma.sync.aligned.m16n8k16.row.col.f32.bf16.bf16.f32 " \
                 "{%0,%1,%2,%3},{%4,%5,%6,%7},{%8,%9},{%0,%1,%2,%3};" \
                 : "+f"((c)[0]), "+f"((c)[1]), "+f"((c)[2]), "+f"((c)[3]) \
                 : "r"((A)[0]), "r"((A)[1]), "r"((A)[2]), "r"((A)[3]), \
                   "r"(b0), "r"(b1))
// A rows 8-15 duplicate rows 0-7 (D rows 8-15 = dup, ignored); a0=k0-7, a1=k8-15
#define MMA_DUP(c, a0, a1, b0, b1) \
    asm volatile("mma.sync.aligned.m16n8k16.row.col.f32.bf16.bf16.f32 " \
                 "{%0,%1,%2,%3},{%4,%5,%6,%7},{%8,%9},{%0,%1,%2,%3};" \
                 : "+f"((c)[0]), "+f"((c)[1]), "+f"((c)[2]), "+f"((c)[3]) \
                 : "r"(a0), "r"(a0), "r"(a1), "r"(a1), "r"(b0), "r"(b1))

// ---------------------------------------------------------------------------
__global__ void detect_done_kernel(const unsigned int* __restrict__ done_words)
{
    int i = blockIdx.x * blockDim.x + threadIdx.x;
    if (done_words[i] > 1u) atomicOr(&g_done_mode, 1);
}

__global__ void decompose_obs(const float* __restrict__ src)
{
    size_t i = (size_t)blockIdx.x * blockDim.x + threadIdx.x;
    float4 v = ((const float4*)src)[i];
    __nv_bfloat16 h0 = __float2bfloat16(v.x);
    __nv_bfloat16 h1 = __float2bfloat16(v.y);
    __nv_bfloat16 h2 = __float2bfloat16(v.z);
    __nv_bfloat16 h3 = __float2bfloat16(v.w);
    __nv_bfloat16 l0 = __float2bfloat16(v.x - __bfloat162float(h0));
    __nv_bfloat16 l1 = __float2bfloat16(v.y - __bfloat162float(h1));
    __nv_bfloat16 l2 = __float2bfloat16(v.z - __bfloat162float(h2));
    __nv_bfloat16 l3 = __float2bfloat16(v.w - __bfloat162float(h3));
    __nv_bfloat162* hp = (__nv_bfloat162*)g_a_hi;
    __nv_bfloat162* lp = (__nv_bfloat162*)g_a_lo;
    hp[2 * i]     = __nv_bfloat162(h0, h1);
    hp[2 * i + 1] = __nv_bfloat162(h2, h3);
    lp[2 * i]     = __nv_bfloat162(l0, l1);
    lp[2 * i + 1] = __nv_bfloat162(l2, l3);
}

__global__ void decompose_wi(const float* __restrict__ Wi)
{
    int idx = blockIdx.x * blockDim.x + threadIdx.x;
    int k = idx / 768, n = idx - k * 768;
    float w = Wi[idx];
    __nv_bfloat16 h = __float2bfloat16(w);
    __nv_bfloat16 l = __float2bfloat16(w - __bfloat162float(h));
    g_wt_hi[n * 256 + k] = h;
    g_wt_lo[n * 256 + k] = l;
}

// ---------------------------------------------------------------------------
// Kernel 1: x_proj GEMM (unchanged from R6, known-good)
// ---------------------------------------------------------------------------
#define STAGE_B 40960
#define OFF_AHI 0
#define OFF_ALO 10240
#define OFF_BHI 20480
#define OFF_BLO 30720
#define XSMEM   (2 * STAGE_B)

__global__ void __launch_bounds__(256, 2)
xproj_mma_kernel(const float* __restrict__ bi)
{
    extern __shared__ char xsm[];
    const int tid = threadIdx.x, wid = tid >> 5, lane = tid & 31;
    const int warp_m = wid & 3, warp_n = wid >> 2;
    const int bN = blockIdx.x * 128;
    const int bM = blockIdx.y * 128;
    const uint32_t sb = smem_u32(xsm);

    const int grp = lane >> 3, r = lane & 7;
    uint32_t aoff[2], boff[4];
#pragma unroll
    for (int mt = 0; mt < 2; mt++)
        aoff[mt] = (uint32_t)((warp_m * 32 + mt * 16 + (grp & 1) * 8 + r) * 80
                              + (grp >> 1) * 16);
#pragma unroll
    for (int np = 0; np < 4; np++)
        boff[np] = (uint32_t)((warp_n * 64 + np * 16 + (grp >> 1) * 8 + r) * 80
                              + (grp & 1) * 16);

    const int c0row = tid >> 2, c0kc = tid & 3;
    const int c1row = (tid + 256) >> 2, c1kc = (tid + 256) & 3;

    auto load_stage = [&](int ks, int buf) {
        const uint32_t s = sb + buf * STAGE_B;
        const int k0 = ks * 32;
        {
            uint32_t so = c0row * 80 + c0kc * 16;
            size_t ga = (size_t)(bM + c0row) * 256 + k0 + c0kc * 8;
            size_t gb = (size_t)(bN + c0row) * 256 + k0 + c0kc * 8;
            cp16(s + OFF_AHI + so, g_a_hi + ga);
            cp16(s + OFF_ALO + so, g_a_lo + ga);
            cp16(s + OFF_BHI + so, g_wt_hi + gb);
            cp16(s + OFF_BLO + so, g_wt_lo + gb);
        }
        {
            uint32_t so = c1row * 80 + c1kc * 16;
            size_t ga = (size_t)(bM + c1row) * 256 + k0 + c1kc * 8;
            size_t gb = (size_t)(bN + c1row) * 256 + k0 + c1kc * 8;
            cp16(s + OFF_AHI + so, g_a_hi + ga);
            cp16(s + OFF_ALO + so, g_a_lo + ga);
            cp16(s + OFF_BHI + so, g_wt_hi + gb);
            cp16(s + OFF_BLO + so, g_wt_lo + gb);
        }
        asm volatile("cp.async.commit_group;" ::: "memory");
    };

    float acc[2][8][4];
#pragma unroll
    for (int mt = 0; mt < 2; mt++)
#pragma unroll
        for (int nt = 0; nt < 8; nt++)
#pragma unroll
            for (int e = 0; e < 4; e++) acc[mt][nt][e] = 0.f;

    load_stage(0, 0);
    load_stage(1, 1);

#pragma unroll 1
    for (int ks = 0; ks < 8; ks++) {
        if (ks < 7)
            asm volatile("cp.async.wait_group 1;" ::: "memory");
        else
            asm volatile("cp.async.wait_group 0;" ::: "memory");
        __syncthreads();

        const uint32_t s = sb + (ks & 1) * STAGE_B;
#pragma unroll
        for (int h = 0; h < 2; h++) {
            uint32_t a[2][2][4];
#pragma unroll
            for (int mt = 0; mt < 2; mt++) {
                LDSM4(a[0][mt], s + OFF_AHI + aoff[mt] + h * 32);
                LDSM4(a[1][mt], s + OFF_ALO + aoff[mt] + h * 32);
            }
#pragma unroll
            for (int np = 0; np < 4; np++) {
                uint32_t bh[4], bl[4];
                LDSM4(bh, s + OFF_BHI + boff[np] + h * 32);
                LDSM4(bl, s + OFF_BLO + boff[np] + h * 32);
#pragma unroll
                for (int mt = 0; mt < 2; mt++) {
                    MMA(acc[mt][2 * np],     a[0][mt], bh[0], bh[1]);
                    MMA(acc[mt][2 * np + 1], a[0][mt], bh[2], bh[3]);
                    MMA(acc[mt][2 * np],     a[0][mt], bl[0], bl[1]);
                    MMA(acc[mt][2 * np + 1], a[0][mt], bl[2], bl[3]);
                    MMA(acc[mt][2 * np],     a[1][mt], bh[0], bh[1]);
                    MMA(acc[mt][2 * np + 1], a[1][mt], bh[2], bh[3]);
                }
            }
        }
        __syncthreads();
        if (ks + 2 < 8) load_stage(ks + 2, ks & 1);
    }

    const int tq = lane >> 2, tr = lane & 3;
#pragma unroll
    for (int mt = 0; mt < 2; mt++) {
#pragma unroll
        for (int nt = 0; nt < 8; nt++) {
            int row = bM + warp_m * 32 + mt * 16 + tq;
            int col = bN + warp_n * 64 + nt * 8 + tr * 2;
            float2 bb = *(const float2*)(bi + col);
            float2 o0 = make_float2(acc[mt][nt][0] + bb.x, acc[mt][nt][1] + bb.y);
            float2 o1 = make_float2(acc[mt][nt][2] + bb.x, acc[mt][nt][3] + bb.y);
            *(float2*)(g_xproj + (size_t)row * 768 + col)       = o0;
            *(float2*)(g_xproj + (size_t)(row + 8) * 768 + col) = o1;
        }
    }
}

// ---------------------------------------------------------------------------
// Kernel 2: GRU scan R16 — R14/R15 stacked-A design plus:
//  (1) all 16 A-LDSM2s batched up front after the wait (MLP burst),
//  (2) ys/out STGs moved into the barrier arrive->wait window.
// ---------------------------------------------------------------------------
#define SBP    528
#define SC_WHI 0
#define SC_WLO (192 * SBP)           // 101376
#define SC_A   (2 * 192 * SBP)       // 202752 ; A[phase][8 rows][SBP]
#define SC_APH (8 * SBP)             // 4224 per phase
#define SC_LO  (4 * SBP)             // lo rows offset within a phase
#define SC_SMEM (SC_A + 2 * SC_APH + 128)

__device__ __forceinline__ float fsigmoid(float x) {
    return __fdividef(1.f, 1.f + __expf(-x));
}
__device__ __forceinline__ float ftanh(float x) {
    return __fdividef(2.f, 1.f + __expf(-2.f * x)) - 1.f;
}

__global__ void __launch_bounds__(256, 1) __cluster_dims__(4, 1, 1)
scan_kernel(const void* __restrict__ done_raw,
            const float* __restrict__ init_h,
            const float* __restrict__ Wh_rz,
            const float* __restrict__ Wh_n,
            const float* __restrict__ bh_n,
            float* __restrict__ out)
{
    extern __shared__ char ssm[];
    const uint32_t sb = smem_u32(ssm);

    const int tid  = threadIdx.x;
    const int rank = blockIdx.x & 3;
    const int b0   = (blockIdx.x >> 2) * 4;

    const int done_mode = g_done_mode;
    const int* done_i32 = (const int*)done_raw;
    const unsigned char* done_u8 = (const unsigned char*)done_raw;

    // --- W slice -> bf16 hi/lo smem [192 n][256 k], pitch SBP ---
    for (int idx = tid; idx < 192 * 256; idx += 256) {
        int n = idx >> 8, k = idx & 255;
        int G = n >> 6, c = n & 63;
        float w = (G < 2) ? Wh_rz[(size_t)k * 512 + G * 256 + rank * 64 + c]
                          : Wh_n[(size_t)k * 256 + rank * 64 + c];
        __nv_bfloat16 hi = __float2bfloat16(w);
        __nv_bfloat16 lo = __float2bfloat16(w - __bfloat162float(hi));
        *(__nv_bfloat16*)(ssm + SC_WHI + n * SBP + k * 2) = hi;
        *(__nv_bfloat16*)(ssm + SC_WLO + n * SBP + k * 2) = lo;
    }
    __syncthreads();

    // --- identities ---
    const int w    = tid >> 5;        // warp 0..7: cols [8w, 8w+8)
    const int lane = tid & 31;
    const int g    = lane >> 2;       // D row for this lane (0-7)
    const int cp   = lane & 3;
    const int jg0  = rank * 64 + 8 * w + 2 * cp;
    const bool is_ew = (lane < 16);   // rows 0-3 = batches

    // B-hi fragments -> registers: 3 gates x 16 chunks x 2 regs
    uint32_t bhreg[3][16][2];
    {
        const int nrow = lane >> 2, kb = (lane & 3) * 4;
#pragma unroll
        for (int G = 0; G < 3; G++) {
            const uint32_t base = (uint32_t)((G * 64 + 8 * w + nrow) * SBP);
#pragma unroll
            for (int c = 0; c < 16; c++) {
                bhreg[G][c][0] = *(const uint32_t*)(ssm + SC_WHI + base + c * 32 + kb);
                bhreg[G][c][1] = *(const uint32_t*)(ssm + SC_WHI + base + c * 32 + kb + 16);
            }
        }
    }

    // ldmatrix lane bases
    const uint32_t a_lane = (uint32_t)((lane & 7) * SBP + ((lane >> 3) & 1) * 16);
    uint32_t bl2[3];
#pragma unroll
    for (int G = 0; G < 3; G++)
        bl2[G] = sb + SC_WLO
            + (uint32_t)((G * 64 + 8 * w + (lane & 7)) * SBP + ((lane >> 3) & 1) * 16);

    // --- per-lane state (ew lanes) ---
    const float2 bb = is_ew ? *(const float2*)(bh_n + jg0) : make_float2(0.f, 0.f);
    const float* xbase = g_xproj + (size_t)(b0 + g) * Tsz * 768 + jg0;
    const size_t done_base = (size_t)(b0 + g) * Tsz;

    float hcur0 = 0.f, hcur1 = 0.f;
    float2 pxr = make_float2(0.f, 0.f), pxz = pxr, pxn = pxr;
    int dn_next = 0;

    if (is_ew) {
        int d0 = done_mode ? (int)done_u8[done_base] : done_i32[done_base];
        float2 h0 = *(const float2*)(init_h + (size_t)(b0 + g) * Hsz + jg0);
        hcur0 = d0 ? 0.f : h0.x;
        hcur1 = d0 ? 0.f : h0.y;
        __nv_bfloat16 ha = __float2bfloat16(hcur0);
        __nv_bfloat16 hb = __float2bfloat16(hcur1);
        __nv_bfloat16 la = __float2bfloat16(hcur0 - __bfloat162float(ha));
        __nv_bfloat16 lb = __float2bfloat16(hcur1 - __bfloat162float(hb));
        uint32_t hp = (uint32_t)__bfloat16_as_ushort(ha)
                    | ((uint32_t)__bfloat16_as_ushort(hb) << 16);
        uint32_t lp = (uint32_t)__bfloat16_as_ushort(la)
                    | ((uint32_t)__bfloat16_as_ushort(lb) << 16);
        uint32_t laddr = sb + SC_A + (uint32_t)(g * SBP + jg0 * 2);
#pragma unroll
        for (uint32_t dst = 0; dst < 4; dst++) {
            uint32_t ra;
            asm volatile("mapa.shared::cluster.u32 %0, %1, %2;"
                         : "=r"(ra) : "r"(laddr), "r"(dst));
            asm volatile("st.shared::cluster.u32 [%0], %1;" :: "r"(ra), "r"(hp) : "memory");
            asm volatile("st.shared::cluster.u32 [%0], %1;"
                         :: "r"(ra + SC_LO), "r"(lp) : "memory");
        }
        pxr = *(const float2*)(xbase);
        pxz = *(const float2*)(xbase + 256);
        pxn = *(const float2*)(xbase + 512);
        dn_next = done_mode ? (int)done_u8[done_base + 1] : done_i32[done_base + 1];
    }
    __syncthreads();
    asm volatile("barrier.cluster.arrive.aligned;" ::: "memory");
    asm volatile("barrier.cluster.wait.aligned;" ::: "memory");

    float* ys = out + Bsz * Hsz;
    int p = 0;

    for (int t = 0; t < Tsz; t++) {
        // ---- batched A loads: 16 chunks of (hi-rows | lo-rows) ----
        const uint32_t a_base = sb + SC_A + p * SC_APH + a_lane;
        uint32_t ar[16][2];
#pragma unroll
        for (int c = 0; c < 16; c++)
            LDSM2(ar[c][0], ar[c][1], a_base + (uint32_t)(c * 32));

        // ---- mma: 3 gates x 16 chunks x 2 products, 6 acc chains ----
        float cg[3][2][4];
#pragma unroll
        for (int G = 0; G < 3; G++)
#pragma unroll
            for (int s = 0; s < 2; s++)
#pragma unroll
                for (int e = 0; e < 4; e++) cg[G][s][e] = 0.f;

#pragma unroll
        for (int c = 0; c < 16; c++) {
            const uint32_t co = (uint32_t)(c * 32);
            uint32_t b0r, b1r, b2r, b3r, b4r, b5r;
            LDSM2(b0r, b1r, bl2[0] + co);
            LDSM2(b2r, b3r, bl2[1] + co);
            LDSM2(b4r, b5r, bl2[2] + co);
            const int s = c & 1;
            MMA_DUP(cg[0][s], ar[c][0], ar[c][1], bhreg[0][c][0], bhreg[0][c][1]);
            MMA_DUP(cg[1][s], ar[c][0], ar[c][1], bhreg[1][c][0], bhreg[1][c][1]);
            MMA_DUP(cg[2][s], ar[c][0], ar[c][1], bhreg[2][c][0], bhreg[2][c][1]);
            MMA_DUP(cg[0][s], ar[c][0], ar[c][1], b0r, b1r);
            MMA_DUP(cg[1][s], ar[c][0], ar[c][1], b2r, b3r);
            MMA_DUP(cg[2][s], ar[c][0], ar[c][1], b4r, b5r);
        }

        // ---- hi/lo row reduction via shfl (all lanes participate) ----
        float sr0 = cg[0][0][0] + cg[0][1][0], sr1 = cg[0][0][1] + cg[0][1][1];
        float sz0 = cg[1][0][0] + cg[1][1][0], sz1 = cg[1][0][1] + cg[1][1][1];
        float sn0 = cg[2][0][0] + cg[2][1][0], sn1 = cg[2][0][1] + cg[2][1][1];
        float hr0 = sr0 + __shfl_down_sync(0xffffffffu, sr0, 16);
        float hr1 = sr1 + __shfl_down_sync(0xffffffffu, sr1, 16);
        float hz0 = sz0 + __shfl_down_sync(0xffffffffu, sz0, 16);
        float hz1 = sz1 + __shfl_down_sync(0xffffffffu, sz1, 16);
        float hn0 = sn0 + __shfl_down_sync(0xffffffffu, sn0, 16);
        float hn1 = sn1 + __shfl_down_sync(0xffffffffu, sn1, 16);

        // ---- fused elementwise (lanes 0-15): compute + broadcast only ----
        float hnew0 = 0.f, hnew1 = 0.f;
        if (is_ew) {
            float r0 = fsigmoid(pxr.x + hr0);
            float r1 = fsigmoid(pxr.y + hr1);
            float z0 = fsigmoid(pxz.x + hz0);
            float z1 = fsigmoid(pxz.y + hz1);
            float n0 = ftanh(pxn.x + r0 * (hn0 + bb.x));
            float n1 = ftanh(pxn.y + r1 * (hn1 + bb.y));
            hnew0 = n0 + z0 * (hcur0 - n0);
            hnew1 = n1 + z1 * (hcur1 - n1);

            float hw0 = dn_next ? 0.f : hnew0;
            float hw1 = dn_next ? 0.f : hnew1;
            hcur0 = hw0;
            hcur1 = hw1;
            __nv_bfloat16 ha = __float2bfloat16(hw0);
            __nv_bfloat16 hb = __float2bfloat16(hw1);
            __nv_bfloat16 la = __float2bfloat16(hw0 - __bfloat162float(ha));
            __nv_bfloat16 lb = __float2bfloat16(hw1 - __bfloat162float(hb));
            uint32_t hp = (uint32_t)__bfloat16_as_ushort(ha)
                        | ((uint32_t)__bfloat16_as_ushort(hb) << 16);
            uint32_t lp = (uint32_t)__bfloat16_as_ushort(la)
                        | ((uint32_t)__bfloat16_as_ushort(lb) << 16);
            uint32_t laddr = sb + SC_A + (uint32_t)((1 - p) * SC_APH + g * SBP + jg0 * 2);
#pragma unroll
            for (uint32_t dst = 0; dst < 4; dst++) {
                uint32_t ra;
                asm volatile("mapa.shared::cluster.u32 %0, %1, %2;"
                             : "=r"(ra) : "r"(laddr), "r"(dst));
                asm volatile("st.shared::cluster.u32 [%0], %1;"
                             :: "r"(ra), "r"(hp) : "memory");
                asm volatile("st.shared::cluster.u32 [%0], %1;"
                             :: "r"(ra + SC_LO), "r"(lp) : "memory");
            }
        }

        asm volatile("barrier.cluster.arrive.aligned;" ::: "memory");
        // ---- deferred work hidden under barrier wait: output stores + prefetch
        if (is_ew) {
            *(float2*)(ys + ((size_t)(b0 + g) * Tsz + t) * Hsz + jg0)
                = make_float2(hnew0, hnew1);
            if (t == Tsz - 1)
                *(float2*)(out + (size_t)(b0 + g) * Hsz + jg0)
                    = make_float2(hnew0, hnew1);
            if (t + 1 < Tsz) {
                const float* xp = xbase + (size_t)(t + 1) * 768;
                pxr = *(const float2*)(xp);
                pxz = *(const float2*)(xp + 256);
                pxn = *(const float2*)(xp + 512);
                if (t + 2 < Tsz) {
                    size_t di = done_base + t + 2;
                    dn_next = done_mode ? (int)done_u8[di] : done_i32[di];
                } else {
                    dn_next = 0;
                }
            }
        }
        asm volatile("barrier.cluster.wait.aligned;" ::: "memory");
        p ^= 1;
    }
}

// ---------------------------------------------------------------------------
// Launch
// ---------------------------------------------------------------------------
extern "C" void kernel_launch(void* const* d_in, const int* in_sizes, int n_in,
                              void* d_out, int out_size)
{
    (void)in_sizes; (void)n_in; (void)out_size;
    const float* obs    = (const float*)d_in[0];
    const void*  done   = d_in[1];
    const float* init_h = (const float*)d_in[2];
    const float* Wi     = (const float*)d_in[3];
    const float* bi     = (const float*)d_in[4];
    const float* Wh_rz  = (const float*)d_in[5];
    const float* Wh_n   = (const float*)d_in[6];
    const float* bh_n   = (const float*)d_in[7];
    float* out = (float*)d_out;

    cudaFuncSetAttribute(scan_kernel, cudaFuncAttributeMaxDynamicSharedMemorySize,
                         SC_SMEM);
    cudaFuncSetAttribute(xproj_mma_kernel, cudaFuncAttributeMaxDynamicSharedMemorySize,
                         XSMEM);

    detect_done_kernel<<<128, 256>>>((const unsigned int*)done);
    decompose_obs<<<32768, 256>>>(obs);
    decompose_wi<<<768, 256>>>(Wi);

    dim3 ggrid(6, 1024);
    xproj_mma_kernel<<<ggrid, 256, XSMEM>>>(bi);

    scan_kernel<<<128, 256, SC_SMEM>>>(done, init_h, Wh_rz, Wh_n, bh_n, out);
}